// round 14
// baseline (speedup 1.0000x reference)
#include <cuda_runtime.h>

#define B_   2
#define H_   12
#define S_   197
#define D_   768
#define HD_  64
#define SS_  (S_*S_)
#define BH_  (B_*H_)
#define LN_EPS 1e-12f
#define NPAIR 78
#define NDOT  209
#define KS2   8            // k-split for the C@W^T GEMM (96 k each)

typedef unsigned long long ull;

// ---------------- scratch (device globals; no allocation) ----------------
__device__ __align__(16) float g_T[BH_*S_*D_];
__device__ __align__(16) float g_tnorm[BH_*S_];
__device__ __align__(16) float g_C[(size_t)B_*S_*D_];      // C[b,i,h*64+v] = P@V
__device__ __align__(16) float g_rs[KS2][B_*S_*D_];        // rowsum partials
__device__ __align__(16) float g_invstd[B_*S_];

__device__ __forceinline__ float wred(float x) {
    #pragma unroll
    for (int o = 16; o; o >>= 1) x += __shfl_xor_sync(0xffffffffu, x, o);
    return x;
}

// ---- packed f32x2 helpers ----
__device__ __forceinline__ ull pack2(float lo, float hi) {
    ull r;
    asm("mov.b64 %0, {%1, %2};" : "=l"(r) : "f"(lo), "f"(hi));
    return r;
}
__device__ __forceinline__ void fma2(ull& d, ull a, ull b) {
    asm("fma.rn.f32x2 %0, %1, %2, %0;" : "+l"(d) : "l"(a), "l"(b));
}
__device__ __forceinline__ ull mul2(ull a, ull b) {
    ull r;
    asm("mul.rn.f32x2 %0, %1, %2;" : "=l"(r) : "l"(a), "l"(b));
    return r;
}
__device__ __forceinline__ ull add2(ull a, ull b) {
    ull r;
    asm("add.rn.f32x2 %0, %1, %2;" : "=l"(r) : "l"(a), "l"(b));
    return r;
}
__device__ __forceinline__ float2 unpack2(ull v) {
    float2 f;
    asm("mov.b64 {%0, %1}, %2;" : "=f"(f.x), "=f"(f.y) : "l"(v));
    return f;
}

// ---------------- transformed GEMM + fused invstd ----------------
__global__ __launch_bounds__(256)
void k_tri(const float* __restrict__ V, const float* __restrict__ W,
           const float* __restrict__ preln)
{
    __shared__ __align__(16) float Vs[64][32];
    __shared__ __align__(16) float Ws[64][128];
    const int tid = threadIdx.x;

    if (blockIdx.z == BH_) {
        __shared__ float sh0[8], sh1[8];
        int q = blockIdx.x * 6 + blockIdx.y;
        for (int row = q; row < B_ * S_; row += 42) {
            const float* x = preln + (size_t)row * D_;
            float s = 0.f, s2 = 0.f;
            #pragma unroll
            for (int k = 0; k < 3; k++) {
                float v = x[tid + k * 256];
                s += v; s2 += v * v;
            }
            s = wred(s); s2 = wred(s2);
            if ((tid & 31) == 0) { sh0[tid >> 5] = s; sh1[tid >> 5] = s2; }
            __syncthreads();
            if (tid == 0) {
                float S = 0.f, S2 = 0.f;
                #pragma unroll
                for (int w = 0; w < 8; w++) { S += sh0[w]; S2 += sh1[w]; }
                float mean = S * (1.f / D_);
                float var  = S2 * (1.f / D_) - mean * mean;
                g_invstd[row] = rsqrtf(var + LN_EPS);
            }
            __syncthreads();
        }
        return;
    }

    const int bh = blockIdx.z;
    const int h  = bh % H_;
    const int s0 = blockIdx.x * 32;
    const int d0 = blockIdx.y * 128;

    for (int idx = tid; idx < 64 * 32; idx += 256) {
        int v = idx >> 5, s = idx & 31;
        int gs = s0 + s;
        Vs[v][s] = (gs < S_) ? V[((size_t)bh * S_ + gs) * HD_ + v] : 0.f;
    }
    for (int idx = tid; idx < 64 * 128; idx += 256) {
        int v = idx >> 7, dd = idx & 127;
        Ws[v][dd] = W[(size_t)(d0 + dd) * D_ + h * HD_ + v];
    }
    __syncthreads();

    const int tx = tid & 31;
    const int ty = tid >> 5;
    ull acc[4][2] = {};
    #pragma unroll
    for (int v = 0; v < 64; v++) {
        float4 vv = *(const float4*)&Vs[v][ty * 4];
        float4 ww = *(const float4*)&Ws[v][tx * 4];
        ull t01 = pack2(ww.x, ww.y), t23 = pack2(ww.z, ww.w);
        ull a0 = pack2(vv.x, vv.x), a1 = pack2(vv.y, vv.y);
        ull a2 = pack2(vv.z, vv.z), a3 = pack2(vv.w, vv.w);
        fma2(acc[0][0], a0, t01); fma2(acc[0][1], a0, t23);
        fma2(acc[1][0], a1, t01); fma2(acc[1][1], a1, t23);
        fma2(acc[2][0], a2, t01); fma2(acc[2][1], a2, t23);
        fma2(acc[3][0], a3, t01); fma2(acc[3][1], a3, t23);
    }
    #pragma unroll
    for (int si = 0; si < 4; si++) {
        int s = s0 + ty * 4 + si;
        if (s < S_) {
            float2 lo = unpack2(acc[si][0]), hi = unpack2(acc[si][1]);
            float4 o = make_float4(lo.x, lo.y, hi.x, hi.y);
            *(float4*)&g_T[((size_t)bh * S_ + s) * D_ + d0 + tx * 4] = o;
        }
    }
}

// ---------------- k_pv: C[b,i,h*64+v] = sum_j P V ----------------
__global__ __launch_bounds__(256)
void k_pv(const float* __restrict__ P, const float* __restrict__ V)
{
    const int bh = blockIdx.z;
    const int b  = bh / H_, h = bh % H_;
    const int i0 = blockIdx.x * 64;
    __shared__ __align__(16) float Ps[32][68];
    __shared__ __align__(16) float Vs[32][64];
    const int tid = threadIdx.x;
    const int tx = tid & 15, ty = tid >> 4;
    ull acc[4][2] = {};

    const float* Pb = P + (size_t)bh * SS_;
    const float* Vb = V + (size_t)bh * S_ * HD_;

    for (int j0 = 0; j0 < S_; j0 += 32) {
        #pragma unroll
        for (int it = 0; it < 8; it++) {
            int idx = tid + it * 256;
            int j = idx & 31, i = idx >> 5;
            int gi = i0 + i, gj = j0 + j;
            Ps[j][i] = (gi < S_ && gj < S_) ? Pb[(size_t)gi * S_ + gj] : 0.f;
        }
        #pragma unroll
        for (int it = 0; it < 2; it++) {
            int idx = tid + it * 256;
            int j = idx >> 4, vq = idx & 15;
            int gj = j0 + j;
            float4 v4 = (gj < S_) ? *(const float4*)&Vb[(size_t)gj * HD_ + vq * 4]
                                  : make_float4(0.f, 0.f, 0.f, 0.f);
            *(float4*)&Vs[j][vq * 4] = v4;
        }
        __syncthreads();
        #pragma unroll 8
        for (int j = 0; j < 32; j++) {
            float4 pv = *(const float4*)&Ps[j][ty * 4];
            float4 vv = *(const float4*)&Vs[j][tx * 4];
            ull t01 = pack2(vv.x, vv.y), t23 = pack2(vv.z, vv.w);
            ull a0 = pack2(pv.x, pv.x), a1 = pack2(pv.y, pv.y);
            ull a2 = pack2(pv.z, pv.z), a3 = pack2(pv.w, pv.w);
            fma2(acc[0][0], a0, t01); fma2(acc[0][1], a0, t23);
            fma2(acc[1][0], a1, t01); fma2(acc[1][1], a1, t23);
            fma2(acc[2][0], a2, t01); fma2(acc[2][1], a2, t23);
            fma2(acc[3][0], a3, t01); fma2(acc[3][1], a3, t23);
        }
        __syncthreads();
    }
    #pragma unroll
    for (int si = 0; si < 4; si++) {
        int gi = i0 + ty * 4 + si;
        if (gi < S_) {
            float2 lo = unpack2(acc[si][0]), hi = unpack2(acc[si][1]);
            float4 o = make_float4(lo.x, lo.y, hi.x, hi.y);
            *(float4*)&g_C[((size_t)(b * S_ + gi)) * D_ + h * HD_ + tx * 4] = o;
        }
    }
}

// ---------------- k_cw: rowsum = C @ W^T, k-split (96 k per split) ----------------
__global__ __launch_bounds__(256)
void k_cw(const float* __restrict__ W)
{
    const int m0 = blockIdx.x * 32;
    const int n0 = blockIdx.y * 128;
    const int split = blockIdx.z;
    __shared__ __align__(16) float Cs[32][36];
    __shared__ __align__(16) float Ws[32][132];
    const int tid = threadIdx.x;
    const int tx = tid & 31, ty = tid >> 5;
    ull acc[4][2] = {};

    for (int kk = 0; kk < 96; kk += 32) {
        const int k0 = split * 96 + kk;
        {
            int m = tid >> 3, kq = tid & 7;
            int gm = m0 + m;
            float4 c4 = (gm < B_ * S_) ? *(const float4*)&g_C[(size_t)gm * D_ + k0 + kq * 4]
                                       : make_float4(0.f, 0.f, 0.f, 0.f);
            Cs[kq * 4 + 0][m] = c4.x; Cs[kq * 4 + 1][m] = c4.y;
            Cs[kq * 4 + 2][m] = c4.z; Cs[kq * 4 + 3][m] = c4.w;
        }
        #pragma unroll
        for (int it = 0; it < 4; it++) {
            int idx = tid + it * 256;
            int n = idx >> 3, kq = idx & 7;
            float4 w4 = *(const float4*)&W[(size_t)(n0 + n) * D_ + k0 + kq * 4];
            Ws[kq * 4 + 0][n] = w4.x; Ws[kq * 4 + 1][n] = w4.y;
            Ws[kq * 4 + 2][n] = w4.z; Ws[kq * 4 + 3][n] = w4.w;
        }
        __syncthreads();
        #pragma unroll 8
        for (int k = 0; k < 32; k++) {
            float4 cm = *(const float4*)&Cs[k][ty * 4];
            float4 wn = *(const float4*)&Ws[k][tx * 4];
            ull t01 = pack2(wn.x, wn.y), t23 = pack2(wn.z, wn.w);
            ull a0 = pack2(cm.x, cm.x), a1 = pack2(cm.y, cm.y);
            ull a2 = pack2(cm.z, cm.z), a3 = pack2(cm.w, cm.w);
            fma2(acc[0][0], a0, t01); fma2(acc[0][1], a0, t23);
            fma2(acc[1][0], a1, t01); fma2(acc[1][1], a1, t23);
            fma2(acc[2][0], a2, t01); fma2(acc[2][1], a2, t23);
            fma2(acc[3][0], a3, t01); fma2(acc[3][1], a3, t23);
        }
        __syncthreads();
    }
    #pragma unroll
    for (int si = 0; si < 4; si++) {
        int gm = m0 + ty * 4 + si;
        if (gm < B_ * S_) {
            float2 lo = unpack2(acc[si][0]), hi = unpack2(acc[si][1]);
            float4 o = make_float4(lo.x, lo.y, hi.x, hi.y);
            *(float4*)&g_rs[split][(size_t)gm * D_ + n0 + tx * 4] = o;
        }
    }
}

// ---------------- scalar kernel: Gram matrices + per-(i,j) norms ----------------
__global__ __launch_bounds__(256)
void k_scal(const float* __restrict__ probs, const float* __restrict__ hidden,
            const float* __restrict__ lnw,
            float* __restrict__ o_sn, float* __restrict__ o_rwn,
            float* __restrict__ o_pln)
{
    const int j = blockIdx.x, b = blockIdx.y;
    const int tid = threadIdx.x;
    const int lane = tid & 31, w = tid >> 5;

    __shared__ float part[NDOT * 8];
    __shared__ float dsm[NDOT];
    __shared__ float Psh[S_ * 13];

    float T[12][3], hd[3], c2[3];
    #pragma unroll
    for (int h = 0; h < 12; h++) {
        const float* tp = g_T + ((size_t)(b * H_ + h) * S_ + j) * D_ + tid;
        #pragma unroll
        for (int k = 0; k < 3; k++) T[h][k] = tp[k * 256];
    }
    {
        const float* hp = hidden + ((size_t)(b * S_ + j)) * D_ + tid;
        const float* cp = lnw + tid;
        #pragma unroll
        for (int k = 0; k < 3; k++) {
            hd[k] = hp[k * 256];
            float c = cp[k * 256];
            c2[k] = c * c;
        }
    }

    for (int idx = tid; idx < H_ * S_; idx += 256) {
        int i = idx / 12, h = idx % 12;
        Psh[i * 13 + h] = probs[((size_t)(b * H_ + h) * S_ + i) * S_ + j];
    }

    {
        int p = 0;
        #pragma unroll
        for (int h = 0; h < 12; h++) {
            #pragma unroll
            for (int h2 = h; h2 < 12; h2++) {
                float q0 = T[h][0] * T[h2][0];
                float q1 = T[h][1] * T[h2][1];
                float q2 = T[h][2] * T[h2][2];
                float g1 = q0 + q1 + q2;
                float g2 = c2[0] * q0 + c2[1] * q1 + c2[2] * q2;
                g1 = wred(g1); g2 = wred(g2);
                if (lane == 0) {
                    part[p * 8 + w]           = g1;
                    part[(NPAIR + p) * 8 + w] = g2;
                }
                p++;
            }
        }
    }
    #pragma unroll
    for (int h = 0; h < 12; h++) {
        float u1 = T[h][0] + T[h][1] + T[h][2];
        float u2 = c2[0] * T[h][0] + c2[1] * T[h][1] + c2[2] * T[h][2];
        float q0 = T[h][0] * hd[0], q1 = T[h][1] * hd[1], q2 = T[h][2] * hd[2];
        float v1 = q0 + q1 + q2;
        float v2 = c2[0] * q0 + c2[1] * q1 + c2[2] * q2;
        u1 = wred(u1); u2 = wred(u2); v1 = wred(v1); v2 = wred(v2);
        if (lane == 0) {
            part[(156 + h) * 8 + w] = u1;
            part[(168 + h) * 8 + w] = u2;
            part[(180 + h) * 8 + w] = v1;
            part[(192 + h) * 8 + w] = v2;
        }
    }
    {
        float e0 = 0.f, e1 = 0.f, e2 = 0.f, e3 = 0.f, cs = 0.f;
        #pragma unroll
        for (int k = 0; k < 3; k++) {
            e0 += hd[k] * hd[k];
            e1 += hd[k];
            e2 += c2[k] * hd[k];
            e3 += c2[k] * hd[k] * hd[k];
            cs += c2[k];
        }
        e0 = wred(e0); e1 = wred(e1); e2 = wred(e2); e3 = wred(e3); cs = wred(cs);
        if (lane == 0) {
            part[204 * 8 + w] = e0; part[205 * 8 + w] = e1;
            part[206 * 8 + w] = e2; part[207 * 8 + w] = e3;
            part[208 * 8 + w] = cs;
        }
    }
    __syncthreads();
    if (tid < NDOT) {
        float s = 0.f;
        #pragma unroll
        for (int k = 0; k < 8; k++) s += part[tid * 8 + k];
        dsm[tid] = s;
    }
    __syncthreads();

    if (tid < 12) {
        int h = tid;
        int pd = h * 12 - (h * (h - 1)) / 2;
        g_tnorm[(b * H_ + h) * S_ + j] = sqrtf(fmaxf(dsm[pd], 0.f));
    }

    if (tid < S_) {
        int i = tid;
        float P[12];
        #pragma unroll
        for (int h = 0; h < 12; h++) P[h] = Psh[i * 13 + h];

        float n1 = 0.f, n3 = 0.f;
        {
            int p = 0;
            #pragma unroll
            for (int h = 0; h < 12; h++) {
                float ph = P[h];
                n1 = fmaf(ph * ph, dsm[p], n1);
                n3 = fmaf(ph * ph, dsm[NPAIR + p], n3);
                p++;
                #pragma unroll
                for (int h2 = h + 1; h2 < 12; h2++) {
                    float pp = 2.f * ph * P[h2];
                    n1 = fmaf(pp, dsm[p], n1);
                    n3 = fmaf(pp, dsm[NPAIR + p], n3);
                    p++;
                }
            }
        }
        float sum_s = 0.f, L = 0.f, sv1 = 0.f, sv2 = 0.f;
        #pragma unroll
        for (int h = 0; h < 12; h++) {
            sum_s = fmaf(P[h], dsm[156 + h], sum_s);
            L     = fmaf(P[h], dsm[168 + h], L);
            sv1   = fmaf(P[h], dsm[180 + h], sv1);
            sv2   = fmaf(P[h], dsm[192 + h], sv2);
        }
        float n2 = n1, Ssum = sum_s, a3 = L, a4 = n3;
        if (i == j) {
            n2   += 2.f * sv1 + dsm[204];
            Ssum += dsm[205];
            a3   += dsm[206];
            a4   += 2.f * sv2 + dsm[207];
        }
        float mean = Ssum * (1.f / D_);
        float is = g_invstd[b * S_ + i];
        int o = (b * S_ + i) * S_ + j;
        o_sn[o]  = sqrtf(fmaxf(n1, 0.f));
        o_rwn[o] = sqrtf(fmaxf(n2, 0.f));
        float pn2 = is * is * (a4 - 2.f * mean * a3 + mean * mean * dsm[208]);
        o_pln[o] = sqrtf(fmaxf(pn2, 0.f));
    }
}

// ---------------- post_ln elementwise: 384 thr x 2 d, one block per (b,j) ----------
__global__ __launch_bounds__(384)
void k_pl(const float* __restrict__ probs, const float* __restrict__ hidden,
          const float* __restrict__ lnw, float* __restrict__ o_pl)
{
    const int j = blockIdx.x, b = blockIdx.y;
    const int tid = threadIdx.x, lane = tid & 31, w = tid >> 5;   // 12 warps
    const int d0 = tid * 2;

    __shared__ __align__(16) ull Pp[S_ * 12];      // 18.9 KB
    __shared__ __align__(16) ull miw[S_][2];       // 3.2 KB
    __shared__ float u1red[13][12];
    __shared__ float u1sh[13];

    float2 Tv[12];
    float tpart[12];
    #pragma unroll
    for (int h = 0; h < 12; h++) {
        Tv[h] = *(const float2*)&g_T[((size_t)(b * H_ + h) * S_ + j) * D_ + d0];
        tpart[h] = Tv[h].x + Tv[h].y;
    }
    const float2 hvf = *(const float2*)&hidden[((size_t)(b * S_ + j)) * D_ + d0];
    const float2 cvf = *(const float2*)&lnw[d0];
    float hpart = hvf.x + hvf.y;

    // gather P column (scattered; overlaps the reductions below)
    for (int idx = tid; idx < S_ * 12; idx += 384) {
        int i = idx / 12, h = idx % 12;
        float v = probs[((size_t)(b * H_ + h) * S_ + i) * S_ + j];
        Pp[idx] = pack2(v, v);
    }

    // block-reduce u1[h] = sum_d T[h,j,d] and hsum
    #pragma unroll
    for (int h = 0; h < 12; h++) {
        float s = wred(tpart[h]);
        if (lane == 0) u1red[h][w] = s;
    }
    {
        float s = wred(hpart);
        if (lane == 0) u1red[12][w] = s;
    }
    __syncthreads();
    if (tid < 13) {
        float s = 0.f;
        #pragma unroll
        for (int k = 0; k < 12; k++) s += u1red[tid][k];
        u1sh[tid] = s;
    }
    __syncthreads();

    // per-i scalars
    for (int i = tid; i < S_; i += 384) {
        float is = g_invstd[b * S_ + i];
        const float* pf = (const float*)&Pp[i * 12];
        float m = 0.f;
        #pragma unroll
        for (int h = 0; h < 12; h++) m = fmaf(pf[2 * h], u1sh[h], m);
        if (i == j) m += u1sh[12];
        m *= (1.f / D_);
        float wv = -m * is;
        miw[i][0] = pack2(is, is);
        miw[i][1] = pack2(wv, wv);
    }

    // fold lnw into T
    ull Tc[12];
    #pragma unroll
    for (int h = 0; h < 12; h++)
        Tc[h] = pack2(Tv[h].x * cvf.x, Tv[h].y * cvf.y);
    const ull chv = pack2(hvf.x * cvf.x, hvf.y * cvf.y);
    const ull cc  = pack2(cvf.x, cvf.y);
    __syncthreads();

    float* dst = &o_pl[((size_t)(b * S_) * S_ + j) * D_ + d0];
    for (int i = 0; i < S_; i++) {
        // two halves to cap transient register pressure
        ull P0[6], P1[6];
        #pragma unroll
        for (int k = 0; k < 3; k++)
            *(ulonglong2*)&P0[k * 2] = *(const ulonglong2*)&Pp[i * 12 + k * 2];
        ull acc = 0ull;
        #pragma unroll
        for (int h = 0; h < 6; h++) fma2(acc, P0[h], Tc[h]);
        #pragma unroll
        for (int k = 0; k < 3; k++)
            *(ulonglong2*)&P1[k * 2] = *(const ulonglong2*)&Pp[i * 12 + 6 + k * 2];
        #pragma unroll
        for (int h = 0; h < 6; h++) fma2(acc, P1[h], Tc[6 + h]);
        if (i == j) acc = add2(acc, chv);
        ulonglong2 mw = *(const ulonglong2*)&miw[i][0];   // .x=is2 .y=w2
        ull o = mul2(cc, mw.y);
        fma2(o, acc, mw.x);
        __stcs((float2*)dst, unpack2(o));
        dst += (size_t)S_ * D_;
    }
}

// ---------------- mixing ratios + weighted_norm ----------------
__global__ __launch_bounds__(768)
void k_mixwn(const float* __restrict__ probs, const float* __restrict__ hidden,
             const float* __restrict__ lnw,
             float* __restrict__ m1, float* __restrict__ m2, float* __restrict__ m3,
             float* __restrict__ wn)
{
    const int blk = blockIdx.x;
    const int b = blk / S_, i = blk % S_;
    const int d = threadIdx.x;
    const int lane = d & 31, w = d >> 5;

    __shared__ float Pd[H_];
    __shared__ float red[5][24];
    __shared__ float bc[8];
    if (d < H_) Pd[d] = probs[((size_t)(b * H_ + d) * S_ + i) * S_ + i];
    __syncthreads();

    float sii = 0.f;
    #pragma unroll
    for (int h = 0; h < H_; h++)
        sii = fmaf(Pd[h], g_T[((size_t)(b * H_ + h) * S_ + i) * D_ + d], sii);

    size_t ridx = ((size_t)(b * S_ + i)) * D_ + d;
    float rs = 0.f;
    #pragma unroll
    for (int k = 0; k < KS2; k++) rs += g_rs[k][ridx];
    float hd   = hidden[ridx];
    float lw   = lnw[d];
    float mixv = rs - sii;
    float rwii = sii + hd;
    float rsrw = rs + hd;

    float a0 = wred(mixv * mixv);
    float a1 = wred(sii * sii);
    float a2 = wred(rwii * rwii);
    float a3 = wred(rwii);
    float a4 = wred(rsrw);
    if (lane == 0) {
        red[0][w] = a0; red[1][w] = a1; red[2][w] = a2;
        red[3][w] = a3; red[4][w] = a4;
    }
    __syncthreads();
    if (d < 5) {
        float sum = 0.f;
        #pragma unroll
        for (int k = 0; k < 24; k++) sum += red[d][k];
        bc[d] = sum;
    }
    __syncthreads();
    float mn1sq = bc[0], pn1sq = bc[1], pn2sq = bc[2];
    float mean_ii = bc[3] * (1.f / D_);
    float M       = bc[4] * (1.f / D_);
    float is = g_invstd[b * S_ + i];

    float pres3 = (rwii - mean_ii) * is * lw;
    float mix3  = is * lw * (rsrw - M) - pres3;
    float b0 = wred(pres3 * pres3);
    float b1 = wred(mix3 * mix3);
    if (lane == 0) { red[0][w] = b0; red[1][w] = b1; }
    __syncthreads();
    if (d == 0) {
        float B0 = 0.f, B1 = 0.f;
        #pragma unroll
        for (int k = 0; k < 24; k++) { B0 += red[0][k]; B1 += red[1][k]; }
        float mn1 = sqrtf(mn1sq), pn1 = sqrtf(pn1sq), pn2 = sqrtf(pn2sq);
        float pn3 = sqrtf(B0),   mn3 = sqrtf(B1);
        m1[b * S_ + i] = mn1 / (mn1 + pn1);
        m2[b * S_ + i] = mn1 / (mn1 + pn2);
        m3[b * S_ + i] = mn3 / (mn3 + pn3);
    }

    for (int idx = blk * 768 + d; idx < BH_ * SS_; idx += B_ * S_ * 768) {
        int bh = idx / SS_;
        int jj = idx % S_;
        __stcs(&wn[idx], probs[idx] * g_tnorm[bh * S_ + jj]);
    }
}

// ---------------- launch: single side stream ----------------
extern "C" void kernel_launch(void* const* d_in, const int* in_sizes, int n_in,
                              void* d_out, int out_size)
{
    const float* hidden = (const float*)d_in[0];
    const float* probs  = (const float*)d_in[1];
    const float* value  = (const float*)d_in[2];
    const float* dw     = (const float*)d_in[3];
    const float* lnw    = (const float*)d_in[4];
    const float* preln  = (const float*)d_in[5];

    float* out   = (float*)d_out;
    float* o_wn  = out;
    float* o_sn  = o_wn  + (size_t)BH_ * SS_;
    float* o_rwn = o_sn  + (size_t)B_ * SS_;
    float* o_pln = o_rwn + (size_t)B_ * SS_;
    float* o_pl  = o_pln + (size_t)B_ * SS_;
    float* o_m1  = o_pl  + (size_t)B_ * SS_ * D_;
    float* o_m2  = o_m1  + B_ * S_;
    float* o_m3  = o_m2  + B_ * S_;

    cudaStream_t s1;
    cudaStreamCreateWithFlags(&s1, cudaStreamNonBlocking);
    cudaEvent_t e0, e_tri, e_mix;
    cudaEventCreateWithFlags(&e0,    cudaEventDisableTiming);
    cudaEventCreateWithFlags(&e_tri, cudaEventDisableTiming);
    cudaEventCreateWithFlags(&e_mix, cudaEventDisableTiming);

    // fork
    cudaEventRecord(e0, 0);
    cudaStreamWaitEvent(s1, e0, 0);

    // s1: pv -> cw -> (wait tri) scal -> mixwn
    k_pv<<<dim3(4, 1, BH_), 256, 0, s1>>>(probs, value);
    k_cw<<<dim3(13, 6, KS2), 256, 0, s1>>>(dw);

    // s0: tri (T + invstd) -> pl
    k_tri<<<dim3(7, 6, BH_ + 1), 256>>>(value, dw, preln);
    cudaEventRecord(e_tri, 0);
    k_pl<<<dim3(S_, B_), 384>>>(probs, hidden, lnw, o_pl);

    // s1 continues: scal (needs g_T via e_tri; overlaps with k_pl on s0)
    cudaStreamWaitEvent(s1, e_tri, 0);
    k_scal<<<dim3(S_, B_), 256, 0, s1>>>(probs, hidden, lnw, o_sn, o_rwn, o_pln);
    k_mixwn<<<B_ * S_, 768, 0, s1>>>(probs, hidden, lnw, o_m1, o_m2, o_m3, o_wn);
    cudaEventRecord(e_mix, s1);

    // join
    cudaStreamWaitEvent(0, e_mix, 0);
}

// round 15
// speedup vs baseline: 1.0737x; 1.0737x over previous
#include <cuda_runtime.h>

#define B_   2
#define H_   12
#define S_   197
#define D_   768
#define HD_  64
#define SS_  (S_*S_)
#define BH_  (B_*H_)
#define LN_EPS 1e-12f
#define NPAIR 78
#define NDOT  209
#define KS2   8            // k-split for the C@W^T GEMM (96 k each)

typedef unsigned long long ull;

// ---------------- scratch (device globals; no allocation) ----------------
__device__ __align__(16) float g_T[BH_*S_*D_];
__device__ __align__(16) float g_tnorm[BH_*S_];
__device__ __align__(16) float g_C[(size_t)B_*S_*D_];      // C[b,i,h*64+v] = P@V
__device__ __align__(16) float g_rs[KS2][B_*S_*D_];        // rowsum partials
__device__ __align__(16) float g_invstd[B_*S_];

__device__ __forceinline__ float wred(float x) {
    #pragma unroll
    for (int o = 16; o; o >>= 1) x += __shfl_xor_sync(0xffffffffu, x, o);
    return x;
}

// ---- packed f32x2 helpers ----
__device__ __forceinline__ ull pack2(float lo, float hi) {
    ull r;
    asm("mov.b64 %0, {%1, %2};" : "=l"(r) : "f"(lo), "f"(hi));
    return r;
}
__device__ __forceinline__ void fma2(ull& d, ull a, ull b) {
    asm("fma.rn.f32x2 %0, %1, %2, %0;" : "+l"(d) : "l"(a), "l"(b));
}
__device__ __forceinline__ ull mul2(ull a, ull b) {
    ull r;
    asm("mul.rn.f32x2 %0, %1, %2;" : "=l"(r) : "l"(a), "l"(b));
    return r;
}
__device__ __forceinline__ float2 unpack2(ull v) {
    float2 f;
    asm("mov.b64 {%0, %1}, %2;" : "=f"(f.x), "=f"(f.y) : "l"(v));
    return f;
}

// ---------------- transformed GEMM + fused invstd ----------------
__global__ __launch_bounds__(256)
void k_tri(const float* __restrict__ V, const float* __restrict__ W,
           const float* __restrict__ preln)
{
    __shared__ __align__(16) float Vs[64][32];
    __shared__ __align__(16) float Ws[64][128];
    const int tid = threadIdx.x;

    if (blockIdx.z == BH_) {
        __shared__ float sh0[8], sh1[8];
        int q = blockIdx.x * 6 + blockIdx.y;
        for (int row = q; row < B_ * S_; row += 42) {
            const float* x = preln + (size_t)row * D_;
            float s = 0.f, s2 = 0.f;
            #pragma unroll
            for (int k = 0; k < 3; k++) {
                float v = x[tid + k * 256];
                s += v; s2 += v * v;
            }
            s = wred(s); s2 = wred(s2);
            if ((tid & 31) == 0) { sh0[tid >> 5] = s; sh1[tid >> 5] = s2; }
            __syncthreads();
            if (tid == 0) {
                float S = 0.f, S2 = 0.f;
                #pragma unroll
                for (int w = 0; w < 8; w++) { S += sh0[w]; S2 += sh1[w]; }
                float mean = S * (1.f / D_);
                float var  = S2 * (1.f / D_) - mean * mean;
                g_invstd[row] = rsqrtf(var + LN_EPS);
            }
            __syncthreads();
        }
        return;
    }

    const int bh = blockIdx.z;
    const int h  = bh % H_;
    const int s0 = blockIdx.x * 32;
    const int d0 = blockIdx.y * 128;

    for (int idx = tid; idx < 64 * 32; idx += 256) {
        int v = idx >> 5, s = idx & 31;
        int gs = s0 + s;
        Vs[v][s] = (gs < S_) ? V[((size_t)bh * S_ + gs) * HD_ + v] : 0.f;
    }
    for (int idx = tid; idx < 64 * 128; idx += 256) {
        int v = idx >> 7, dd = idx & 127;
        Ws[v][dd] = W[(size_t)(d0 + dd) * D_ + h * HD_ + v];
    }
    __syncthreads();

    const int tx = tid & 31;
    const int ty = tid >> 5;
    ull acc[4][2] = {};
    #pragma unroll
    for (int v = 0; v < 64; v++) {
        float4 vv = *(const float4*)&Vs[v][ty * 4];
        float4 ww = *(const float4*)&Ws[v][tx * 4];
        ull t01 = pack2(ww.x, ww.y), t23 = pack2(ww.z, ww.w);
        ull a0 = pack2(vv.x, vv.x), a1 = pack2(vv.y, vv.y);
        ull a2 = pack2(vv.z, vv.z), a3 = pack2(vv.w, vv.w);
        fma2(acc[0][0], a0, t01); fma2(acc[0][1], a0, t23);
        fma2(acc[1][0], a1, t01); fma2(acc[1][1], a1, t23);
        fma2(acc[2][0], a2, t01); fma2(acc[2][1], a2, t23);
        fma2(acc[3][0], a3, t01); fma2(acc[3][1], a3, t23);
    }
    #pragma unroll
    for (int si = 0; si < 4; si++) {
        int s = s0 + ty * 4 + si;
        if (s < S_) {
            float2 lo = unpack2(acc[si][0]), hi = unpack2(acc[si][1]);
            float4 o = make_float4(lo.x, lo.y, hi.x, hi.y);
            *(float4*)&g_T[((size_t)bh * S_ + s) * D_ + d0 + tx * 4] = o;
        }
    }
}

// ---------------- k_pv: C[b,i,h*64+v] = sum_j P V ----------------
__global__ __launch_bounds__(256)
void k_pv(const float* __restrict__ P, const float* __restrict__ V)
{
    const int bh = blockIdx.z;
    const int b  = bh / H_, h = bh % H_;
    const int i0 = blockIdx.x * 64;
    __shared__ __align__(16) float Ps[32][68];
    __shared__ __align__(16) float Vs[32][64];
    const int tid = threadIdx.x;
    const int tx = tid & 15, ty = tid >> 4;
    ull acc[4][2] = {};

    const float* Pb = P + (size_t)bh * SS_;
    const float* Vb = V + (size_t)bh * S_ * HD_;

    for (int j0 = 0; j0 < S_; j0 += 32) {
        #pragma unroll
        for (int it = 0; it < 8; it++) {
            int idx = tid + it * 256;
            int j = idx & 31, i = idx >> 5;
            int gi = i0 + i, gj = j0 + j;
            Ps[j][i] = (gi < S_ && gj < S_) ? Pb[(size_t)gi * S_ + gj] : 0.f;
        }
        #pragma unroll
        for (int it = 0; it < 2; it++) {
            int idx = tid + it * 256;
            int j = idx >> 4, vq = idx & 15;
            int gj = j0 + j;
            float4 v4 = (gj < S_) ? *(const float4*)&Vb[(size_t)gj * HD_ + vq * 4]
                                  : make_float4(0.f, 0.f, 0.f, 0.f);
            *(float4*)&Vs[j][vq * 4] = v4;
        }
        __syncthreads();
        #pragma unroll 8
        for (int j = 0; j < 32; j++) {
            float4 pv = *(const float4*)&Ps[j][ty * 4];
            float4 vv = *(const float4*)&Vs[j][tx * 4];
            ull t01 = pack2(vv.x, vv.y), t23 = pack2(vv.z, vv.w);
            ull a0 = pack2(pv.x, pv.x), a1 = pack2(pv.y, pv.y);
            ull a2 = pack2(pv.z, pv.z), a3 = pack2(pv.w, pv.w);
            fma2(acc[0][0], a0, t01); fma2(acc[0][1], a0, t23);
            fma2(acc[1][0], a1, t01); fma2(acc[1][1], a1, t23);
            fma2(acc[2][0], a2, t01); fma2(acc[2][1], a2, t23);
            fma2(acc[3][0], a3, t01); fma2(acc[3][1], a3, t23);
        }
        __syncthreads();
    }
    #pragma unroll
    for (int si = 0; si < 4; si++) {
        int gi = i0 + ty * 4 + si;
        if (gi < S_) {
            float2 lo = unpack2(acc[si][0]), hi = unpack2(acc[si][1]);
            float4 o = make_float4(lo.x, lo.y, hi.x, hi.y);
            *(float4*)&g_C[((size_t)(b * S_ + gi)) * D_ + h * HD_ + tx * 4] = o;
        }
    }
}

// ---------------- k_cw: rowsum = C @ W^T, k-split (96 k per split) ----------------
__global__ __launch_bounds__(256)
void k_cw(const float* __restrict__ W)
{
    const int m0 = blockIdx.x * 32;
    const int n0 = blockIdx.y * 128;
    const int split = blockIdx.z;
    __shared__ __align__(16) float Cs[32][36];
    __shared__ __align__(16) float Ws[32][132];
    const int tid = threadIdx.x;
    const int tx = tid & 31, ty = tid >> 5;
    ull acc[4][2] = {};

    for (int kk = 0; kk < 96; kk += 32) {
        const int k0 = split * 96 + kk;
        {
            int m = tid >> 3, kq = tid & 7;
            int gm = m0 + m;
            float4 c4 = (gm < B_ * S_) ? *(const float4*)&g_C[(size_t)gm * D_ + k0 + kq * 4]
                                       : make_float4(0.f, 0.f, 0.f, 0.f);
            Cs[kq * 4 + 0][m] = c4.x; Cs[kq * 4 + 1][m] = c4.y;
            Cs[kq * 4 + 2][m] = c4.z; Cs[kq * 4 + 3][m] = c4.w;
        }
        #pragma unroll
        for (int it = 0; it < 4; it++) {
            int idx = tid + it * 256;
            int n = idx >> 3, kq = idx & 7;
            float4 w4 = *(const float4*)&W[(size_t)(n0 + n) * D_ + k0 + kq * 4];
            Ws[kq * 4 + 0][n] = w4.x; Ws[kq * 4 + 1][n] = w4.y;
            Ws[kq * 4 + 2][n] = w4.z; Ws[kq * 4 + 3][n] = w4.w;
        }
        __syncthreads();
        #pragma unroll 8
        for (int k = 0; k < 32; k++) {
            float4 cm = *(const float4*)&Cs[k][ty * 4];
            float4 wn = *(const float4*)&Ws[k][tx * 4];
            ull t01 = pack2(wn.x, wn.y), t23 = pack2(wn.z, wn.w);
            ull a0 = pack2(cm.x, cm.x), a1 = pack2(cm.y, cm.y);
            ull a2 = pack2(cm.z, cm.z), a3 = pack2(cm.w, cm.w);
            fma2(acc[0][0], a0, t01); fma2(acc[0][1], a0, t23);
            fma2(acc[1][0], a1, t01); fma2(acc[1][1], a1, t23);
            fma2(acc[2][0], a2, t01); fma2(acc[2][1], a2, t23);
            fma2(acc[3][0], a3, t01); fma2(acc[3][1], a3, t23);
        }
        __syncthreads();
    }
    #pragma unroll
    for (int si = 0; si < 4; si++) {
        int gm = m0 + ty * 4 + si;
        if (gm < B_ * S_) {
            float2 lo = unpack2(acc[si][0]), hi = unpack2(acc[si][1]);
            float4 o = make_float4(lo.x, lo.y, hi.x, hi.y);
            *(float4*)&g_rs[split][(size_t)gm * D_ + n0 + tx * 4] = o;
        }
    }
}

// ---------------- scalar kernel: Gram matrices + per-(i,j) norms ----------------
__global__ __launch_bounds__(256)
void k_scal(const float* __restrict__ probs, const float* __restrict__ hidden,
            const float* __restrict__ lnw,
            float* __restrict__ o_sn, float* __restrict__ o_rwn,
            float* __restrict__ o_pln)
{
    const int j = blockIdx.x, b = blockIdx.y;
    const int tid = threadIdx.x;
    const int lane = tid & 31, w = tid >> 5;

    __shared__ float part[NDOT * 8];
    __shared__ float dsm[NDOT];
    __shared__ float Psh[S_ * 13];

    float T[12][3], hd[3], c2[3];
    #pragma unroll
    for (int h = 0; h < 12; h++) {
        const float* tp = g_T + ((size_t)(b * H_ + h) * S_ + j) * D_ + tid;
        #pragma unroll
        for (int k = 0; k < 3; k++) T[h][k] = tp[k * 256];
    }
    {
        const float* hp = hidden + ((size_t)(b * S_ + j)) * D_ + tid;
        const float* cp = lnw + tid;
        #pragma unroll
        for (int k = 0; k < 3; k++) {
            hd[k] = hp[k * 256];
            float c = cp[k * 256];
            c2[k] = c * c;
        }
    }

    for (int idx = tid; idx < H_ * S_; idx += 256) {
        int i = idx / 12, h = idx % 12;
        Psh[i * 13 + h] = probs[((size_t)(b * H_ + h) * S_ + i) * S_ + j];
    }

    {
        int p = 0;
        #pragma unroll
        for (int h = 0; h < 12; h++) {
            #pragma unroll
            for (int h2 = h; h2 < 12; h2++) {
                float q0 = T[h][0] * T[h2][0];
                float q1 = T[h][1] * T[h2][1];
                float q2 = T[h][2] * T[h2][2];
                float g1 = q0 + q1 + q2;
                float g2 = c2[0] * q0 + c2[1] * q1 + c2[2] * q2;
                g1 = wred(g1); g2 = wred(g2);
                if (lane == 0) {
                    part[p * 8 + w]           = g1;
                    part[(NPAIR + p) * 8 + w] = g2;
                }
                p++;
            }
        }
    }
    #pragma unroll
    for (int h = 0; h < 12; h++) {
        float u1 = T[h][0] + T[h][1] + T[h][2];
        float u2 = c2[0] * T[h][0] + c2[1] * T[h][1] + c2[2] * T[h][2];
        float q0 = T[h][0] * hd[0], q1 = T[h][1] * hd[1], q2 = T[h][2] * hd[2];
        float v1 = q0 + q1 + q2;
        float v2 = c2[0] * q0 + c2[1] * q1 + c2[2] * q2;
        u1 = wred(u1); u2 = wred(u2); v1 = wred(v1); v2 = wred(v2);
        if (lane == 0) {
            part[(156 + h) * 8 + w] = u1;
            part[(168 + h) * 8 + w] = u2;
            part[(180 + h) * 8 + w] = v1;
            part[(192 + h) * 8 + w] = v2;
        }
    }
    {
        float e0 = 0.f, e1 = 0.f, e2 = 0.f, e3 = 0.f, cs = 0.f;
        #pragma unroll
        for (int k = 0; k < 3; k++) {
            e0 += hd[k] * hd[k];
            e1 += hd[k];
            e2 += c2[k] * hd[k];
            e3 += c2[k] * hd[k] * hd[k];
            cs += c2[k];
        }
        e0 = wred(e0); e1 = wred(e1); e2 = wred(e2); e3 = wred(e3); cs = wred(cs);
        if (lane == 0) {
            part[204 * 8 + w] = e0; part[205 * 8 + w] = e1;
            part[206 * 8 + w] = e2; part[207 * 8 + w] = e3;
            part[208 * 8 + w] = cs;
        }
    }
    __syncthreads();
    if (tid < NDOT) {
        float s = 0.f;
        #pragma unroll
        for (int k = 0; k < 8; k++) s += part[tid * 8 + k];
        dsm[tid] = s;
    }
    __syncthreads();

    if (tid < 12) {
        int h = tid;
        int pd = h * 12 - (h * (h - 1)) / 2;
        g_tnorm[(b * H_ + h) * S_ + j] = sqrtf(fmaxf(dsm[pd], 0.f));
    }

    if (tid < S_) {
        int i = tid;
        float P[12];
        #pragma unroll
        for (int h = 0; h < 12; h++) P[h] = Psh[i * 13 + h];

        float n1 = 0.f, n3 = 0.f;
        {
            int p = 0;
            #pragma unroll
            for (int h = 0; h < 12; h++) {
                float ph = P[h];
                n1 = fmaf(ph * ph, dsm[p], n1);
                n3 = fmaf(ph * ph, dsm[NPAIR + p], n3);
                p++;
                #pragma unroll
                for (int h2 = h + 1; h2 < 12; h2++) {
                    float pp = 2.f * ph * P[h2];
                    n1 = fmaf(pp, dsm[p], n1);
                    n3 = fmaf(pp, dsm[NPAIR + p], n3);
                    p++;
                }
            }
        }
        float sum_s = 0.f, L = 0.f, sv1 = 0.f, sv2 = 0.f;
        #pragma unroll
        for (int h = 0; h < 12; h++) {
            sum_s = fmaf(P[h], dsm[156 + h], sum_s);
            L     = fmaf(P[h], dsm[168 + h], L);
            sv1   = fmaf(P[h], dsm[180 + h], sv1);
            sv2   = fmaf(P[h], dsm[192 + h], sv2);
        }
        float n2 = n1, Ssum = sum_s, a3 = L, a4 = n3;
        if (i == j) {
            n2   += 2.f * sv1 + dsm[204];
            Ssum += dsm[205];
            a3   += dsm[206];
            a4   += 2.f * sv2 + dsm[207];
        }
        float mean = Ssum * (1.f / D_);
        float is = g_invstd[b * S_ + i];
        int o = (b * S_ + i) * S_ + j;
        o_sn[o]  = sqrtf(fmaxf(n1, 0.f));
        o_rwn[o] = sqrtf(fmaxf(n2, 0.f));
        float pn2 = is * is * (a4 - 2.f * mean * a3 + mean * mean * dsm[208]);
        o_pln[o] = sqrtf(fmaxf(pn2, 0.f));
    }
}

// ---------------- post_ln: 192 thr x 4 d, h-paired FFMA2, P as raw floats ------
// LDS per iter: 3x LDS.128 (P) + 1x LDS.64 (miw) -- down from 7x LDS.128.
__global__ __launch_bounds__(192)
void k_pl(const float* __restrict__ probs, const float* __restrict__ hidden,
          const float* __restrict__ lnw, float* __restrict__ o_pl)
{
    const int j = blockIdx.x, b = blockIdx.y, half = blockIdx.z;
    const int tid = threadIdx.x, lane = tid & 31, w = tid >> 5;
    const int d0 = tid * 4;
    const int i0 = half ? 99 : 0;
    const int nI = half ? (S_ - 99) : 99;

    __shared__ __align__(16) float  Pf[99 * 12];   // raw floats, stride 12 (48B, 16B-aligned)
    __shared__ __align__(16) float2 miw[99];       // (is, -m*is)
    __shared__ float u1red[13][6];
    __shared__ float u1sh[13];

    float4 Tv[12];
    float tpart[12];
    #pragma unroll
    for (int h = 0; h < 12; h++) {
        Tv[h] = *(const float4*)&g_T[((size_t)(b * H_ + h) * S_ + j) * D_ + d0];
        tpart[h] = (Tv[h].x + Tv[h].y) + (Tv[h].z + Tv[h].w);
    }
    const float4 hvf = *(const float4*)&hidden[((size_t)(b * S_ + j)) * D_ + d0];
    const float4 cvf = *(const float4*)&lnw[d0];
    float hpart = (hvf.x + hvf.y) + (hvf.z + hvf.w);

    // gather P column (scattered; overlaps reductions below)
    for (int idx = tid; idx < nI * 12; idx += 192) {
        int il = idx / 12, h = idx % 12;
        Pf[idx] = probs[((size_t)(b * H_ + h) * S_ + (i0 + il)) * S_ + j];
    }

    // block-reduce u1[h] = sum_d T[h,j,d] and hsum
    #pragma unroll
    for (int h = 0; h < 12; h++) {
        float s = wred(tpart[h]);
        if (lane == 0) u1red[h][w] = s;
    }
    {
        float s = wred(hpart);
        if (lane == 0) u1red[12][w] = s;
    }
    __syncthreads();
    if (tid < 13) {
        float s = 0.f;
        #pragma unroll
        for (int k = 0; k < 6; k++) s += u1red[tid][k];
        u1sh[tid] = s;
    }
    __syncthreads();

    // per-i scalars: (is, -m*is)
    for (int il = tid; il < nI; il += 192) {
        int gi = i0 + il;
        float is = g_invstd[b * S_ + gi];
        const float* pf = &Pf[il * 12];
        float m = 0.f;
        #pragma unroll
        for (int h = 0; h < 12; h++) m = fmaf(pf[h], u1sh[h], m);
        if (gi == j) m += u1sh[12];
        m *= (1.f / D_);
        miw[il] = make_float2(is, -m * is);
    }

    // Tc[d][hp] = (c_d*T[2hp,d], c_d*T[2hp+1,d])  -- h-paired
    ull Tc[4][6];
    #pragma unroll
    for (int hp = 0; hp < 6; hp++) {
        Tc[0][hp] = pack2(Tv[2*hp].x * cvf.x, Tv[2*hp+1].x * cvf.x);
        Tc[1][hp] = pack2(Tv[2*hp].y * cvf.y, Tv[2*hp+1].y * cvf.y);
        Tc[2][hp] = pack2(Tv[2*hp].z * cvf.z, Tv[2*hp+1].z * cvf.z);
        Tc[3][hp] = pack2(Tv[2*hp].w * cvf.w, Tv[2*hp+1].w * cvf.w);
    }
    const float chv0 = hvf.x * cvf.x, chv1 = hvf.y * cvf.y;
    const float chv2 = hvf.z * cvf.z, chv3 = hvf.w * cvf.w;
    __syncthreads();

    float* dst = &o_pl[((size_t)(b * S_ + i0) * S_ + j) * D_ + d0];
    for (int il = 0; il < nI; il++) {
        const float4* pf4 = (const float4*)&Pf[il * 12];
        float4 p0 = pf4[0], p1 = pf4[1], p2 = pf4[2];      // 3x LDS.128
        ull q0 = pack2(p0.x, p0.y), q1 = pack2(p0.z, p0.w); // adjacent-reg pairs: free
        ull q2 = pack2(p1.x, p1.y), q3 = pack2(p1.z, p1.w);
        ull q4 = pack2(p2.x, p2.y), q5 = pack2(p2.z, p2.w);
        ull a0 = 0ull, a1 = 0ull, a2 = 0ull, a3 = 0ull;
        fma2(a0, q0, Tc[0][0]); fma2(a1, q0, Tc[1][0]); fma2(a2, q0, Tc[2][0]); fma2(a3, q0, Tc[3][0]);
        fma2(a0, q1, Tc[0][1]); fma2(a1, q1, Tc[1][1]); fma2(a2, q1, Tc[2][1]); fma2(a3, q1, Tc[3][1]);
        fma2(a0, q2, Tc[0][2]); fma2(a1, q2, Tc[1][2]); fma2(a2, q2, Tc[2][2]); fma2(a3, q2, Tc[3][2]);
        fma2(a0, q3, Tc[0][3]); fma2(a1, q3, Tc[1][3]); fma2(a2, q3, Tc[2][3]); fma2(a3, q3, Tc[3][3]);
        fma2(a0, q4, Tc[0][4]); fma2(a1, q4, Tc[1][4]); fma2(a2, q4, Tc[2][4]); fma2(a3, q4, Tc[3][4]);
        fma2(a0, q5, Tc[0][5]); fma2(a1, q5, Tc[1][5]); fma2(a2, q5, Tc[2][5]); fma2(a3, q5, Tc[3][5]);
        float2 f0 = unpack2(a0), f1 = unpack2(a1), f2 = unpack2(a2), f3 = unpack2(a3);
        float s0 = f0.x + f0.y, s1 = f1.x + f1.y;           // horizontal: even+odd h
        float s2 = f2.x + f2.y, s3 = f3.x + f3.y;
        if (i0 + il == j) { s0 += chv0; s1 += chv1; s2 += chv2; s3 += chv3; }
        float2 mw = miw[il];                                // LDS.64: (is, w)
        float wc0 = mw.y * cvf.x, wc1 = mw.y * cvf.y;
        float wc2 = mw.y * cvf.z, wc3 = mw.y * cvf.w;
        float2 oa, ob;
        oa.x = fmaf(s0, mw.x, wc0);
        oa.y = fmaf(s1, mw.x, wc1);
        ob.x = fmaf(s2, mw.x, wc2);
        ob.y = fmaf(s3, mw.x, wc3);
        __stcs((float2*)dst,       oa);
        __stcs((float2*)(dst + 2), ob);
        dst += (size_t)S_ * D_;
    }
}

// ---------------- mixing ratios + weighted_norm ----------------
__global__ __launch_bounds__(768)
void k_mixwn(const float* __restrict__ probs, const float* __restrict__ hidden,
             const float* __restrict__ lnw,
             float* __restrict__ m1, float* __restrict__ m2, float* __restrict__ m3,
             float* __restrict__ wn)
{
    const int blk = blockIdx.x;
    const int b = blk / S_, i = blk % S_;
    const int d = threadIdx.x;
    const int lane = d & 31, w = d >> 5;

    __shared__ float Pd[H_];
    __shared__ float red[5][24];
    __shared__ float bc[8];
    if (d < H_) Pd[d] = probs[((size_t)(b * H_ + d) * S_ + i) * S_ + i];
    __syncthreads();

    float sii = 0.f;
    #pragma unroll
    for (int h = 0; h < H_; h++)
        sii = fmaf(Pd[h], g_T[((size_t)(b * H_ + h) * S_ + i) * D_ + d], sii);

    size_t ridx = ((size_t)(b * S_ + i)) * D_ + d;
    float rs = 0.f;
    #pragma unroll
    for (int k = 0; k < KS2; k++) rs += g_rs[k][ridx];
    float hd   = hidden[ridx];
    float lw   = lnw[d];
    float mixv = rs - sii;
    float rwii = sii + hd;
    float rsrw = rs + hd;

    float a0 = wred(mixv * mixv);
    float a1 = wred(sii * sii);
    float a2 = wred(rwii * rwii);
    float a3 = wred(rwii);
    float a4 = wred(rsrw);
    if (lane == 0) {
        red[0][w] = a0; red[1][w] = a1; red[2][w] = a2;
        red[3][w] = a3; red[4][w] = a4;
    }
    __syncthreads();
    if (d < 5) {
        float sum = 0.f;
        #pragma unroll
        for (int k = 0; k < 24; k++) sum += red[d][k];
        bc[d] = sum;
    }
    __syncthreads();
    float mn1sq = bc[0], pn1sq = bc[1], pn2sq = bc[2];
    float mean_ii = bc[3] * (1.f / D_);
    float M       = bc[4] * (1.f / D_);
    float is = g_invstd[b * S_ + i];

    float pres3 = (rwii - mean_ii) * is * lw;
    float mix3  = is * lw * (rsrw - M) - pres3;
    float b0 = wred(pres3 * pres3);
    float b1 = wred(mix3 * mix3);
    if (lane == 0) { red[0][w] = b0; red[1][w] = b1; }
    __syncthreads();
    if (d == 0) {
        float B0 = 0.f, B1 = 0.f;
        #pragma unroll
        for (int k = 0; k < 24; k++) { B0 += red[0][k]; B1 += red[1][k]; }
        float mn1 = sqrtf(mn1sq), pn1 = sqrtf(pn1sq), pn2 = sqrtf(pn2sq);
        float pn3 = sqrtf(B0),   mn3 = sqrtf(B1);
        m1[b * S_ + i] = mn1 / (mn1 + pn1);
        m2[b * S_ + i] = mn1 / (mn1 + pn2);
        m3[b * S_ + i] = mn3 / (mn3 + pn3);
    }

    for (int idx = blk * 768 + d; idx < BH_ * SS_; idx += B_ * S_ * 768) {
        int bh = idx / SS_;
        int jj = idx % S_;
        __stcs(&wn[idx], probs[idx] * g_tnorm[bh * S_ + jj]);
    }
}

// ---------------- launch: single side stream ----------------
extern "C" void kernel_launch(void* const* d_in, const int* in_sizes, int n_in,
                              void* d_out, int out_size)
{
    const float* hidden = (const float*)d_in[0];
    const float* probs  = (const float*)d_in[1];
    const float* value  = (const float*)d_in[2];
    const float* dw     = (const float*)d_in[3];
    const float* lnw    = (const float*)d_in[4];
    const float* preln  = (const float*)d_in[5];

    float* out   = (float*)d_out;
    float* o_wn  = out;
    float* o_sn  = o_wn  + (size_t)BH_ * SS_;
    float* o_rwn = o_sn  + (size_t)B_ * SS_;
    float* o_pln = o_rwn + (size_t)B_ * SS_;
    float* o_pl  = o_pln + (size_t)B_ * SS_;
    float* o_m1  = o_pl  + (size_t)B_ * SS_ * D_;
    float* o_m2  = o_m1  + B_ * S_;
    float* o_m3  = o_m2  + B_ * S_;

    cudaStream_t s1;
    cudaStreamCreateWithFlags(&s1, cudaStreamNonBlocking);
    cudaEvent_t e0, e_tri, e_mix;
    cudaEventCreateWithFlags(&e0,    cudaEventDisableTiming);
    cudaEventCreateWithFlags(&e_tri, cudaEventDisableTiming);
    cudaEventCreateWithFlags(&e_mix, cudaEventDisableTiming);

    // fork
    cudaEventRecord(e0, 0);
    cudaStreamWaitEvent(s1, e0, 0);

    // s1: pv -> cw -> (wait tri) scal -> mixwn
    k_pv<<<dim3(4, 1, BH_), 256, 0, s1>>>(probs, value);
    k_cw<<<dim3(13, 6, KS2), 256, 0, s1>>>(dw);

    // s0: tri (T + invstd) -> pl
    k_tri<<<dim3(7, 6, BH_ + 1), 256>>>(value, dw, preln);
    cudaEventRecord(e_tri, 0);
    k_pl<<<dim3(S_, B_, 2), 192>>>(probs, hidden, lnw, o_pl);

    // s1 continues: scal (needs g_T via e_tri; overlaps with k_pl on s0)
    cudaStreamWaitEvent(s1, e_tri, 0);
    k_scal<<<dim3(S_, B_), 256, 0, s1>>>(probs, hidden, lnw, o_sn, o_rwn, o_pln);
    k_mixwn<<<B_ * S_, 768, 0, s1>>>(probs, hidden, lnw, o_m1, o_m2, o_m3, o_wn);
    cudaEventRecord(e_mix, s1);

    // join
    cudaStreamWaitEvent(0, e_mix, 0);
}